// round 13
// baseline (speedup 1.0000x reference)
#include <cuda_runtime.h>
#include <cuda_fp16.h>
#include <cstdint>

// Problem constants
#define NB   32      // batch
#define NN   1024    // nodes per graph
#define NF   128     // in features
#define NH   128     // hidden features

// fp16 scratch for support = fp16(x @ W)  (static -> allocation-guard safe)
// GEMM-2 (single-pass) only ever consumes fp16(support), so storing fp32 was waste.
__device__ __half g_support_h[(size_t)NB * NN * NH];   // 8 MB

// ===========================================================================
// PTX helpers (baseline sm_80-class instructions -> compile on compute_103)
// ===========================================================================
__device__ __forceinline__ uint32_t smem_to_u32(const void* p) {
    uint32_t a;
    asm("{ .reg .u64 t; cvta.to.shared.u64 t, %1; cvt.u32.u64 %0, t; }" : "=r"(a) : "l"(p));
    return a;
}

#define LDSM4(R, addr) \
    asm volatile("ldmatrix.sync.aligned.m8n8.x4.shared.b16 {%0,%1,%2,%3}, [%4];" \
        : "=r"((R)[0]), "=r"((R)[1]), "=r"((R)[2]), "=r"((R)[3]) : "r"(addr))

#define LDSM4T(R, addr) \
    asm volatile("ldmatrix.sync.aligned.m8n8.x4.trans.shared.b16 {%0,%1,%2,%3}, [%4];" \
        : "=r"((R)[0]), "=r"((R)[1]), "=r"((R)[2]), "=r"((R)[3]) : "r"(addr))

#define MMA16816(C, A, b0, b1) \
    asm volatile("mma.sync.aligned.m16n8k16.row.col.f32.f16.f16.f32 " \
        "{%0,%1,%2,%3},{%4,%5,%6,%7},{%8,%9},{%0,%1,%2,%3};" \
        : "+f"((C)[0]), "+f"((C)[1]), "+f"((C)[2]), "+f"((C)[3]) \
        : "r"((A)[0]), "r"((A)[1]), "r"((A)[2]), "r"((A)[3]), "r"(b0), "r"(b1))

#define CP_ASYNC16(dst, src) \
    asm volatile("cp.async.ca.shared.global [%0], [%1], 16;" :: "r"(dst), "l"(src))
#define CP_COMMIT() asm volatile("cp.async.commit_group;" ::: "memory")
#define CP_WAIT1()  asm volatile("cp.async.wait_group 1;"  ::: "memory")
#define CP_WAIT0()  asm volatile("cp.async.wait_group 0;"  ::: "memory")

__device__ __forceinline__ uint32_t pack_h2(__half a, __half b) {
    __half2 t = __halves2half2(a, b);
    return *reinterpret_cast<uint32_t*>(&t);
}

// fp32 -> (hi fp16, lo fp16) split of a float4
__device__ __forceinline__ void split4(float4 v, uint2& hu, uint2& lu) {
    __half h0 = __float2half_rn(v.x), h1 = __float2half_rn(v.y);
    __half h2 = __float2half_rn(v.z), h3 = __float2half_rn(v.w);
    __half l0 = __float2half_rn(v.x - __half2float(h0));
    __half l1 = __float2half_rn(v.y - __half2float(h1));
    __half l2 = __float2half_rn(v.z - __half2float(h2));
    __half l3 = __float2half_rn(v.w - __half2float(h3));
    hu.x = pack_h2(h0, h1); hu.y = pack_h2(h2, h3);
    lu.x = pack_h2(l0, l1); lu.y = pack_h2(l2, l3);
}

// fp32 -> hi fp16 only
__device__ __forceinline__ void split4hi(float4 v, uint2& hu) {
    hu.x = pack_h2(__float2half_rn(v.x), __float2half_rn(v.y));
    hu.y = pack_h2(__float2half_rn(v.z), __float2half_rn(v.w));
}

// ===========================================================================
// GEMM-1 (3-pass split-fp16): support_h = fp16(x @ W)
//   CTA: 128x128, 512 threads = 16 warps (4m x 4n), warp tile 32x32, BK=32.
//   Same structure as the proven round-11 kernel; epilogue stores fp16.
// ===========================================================================
#define RSA   80        // A smem row stride bytes (32+8 halves)
#define RSB   272       // B smem row stride bytes (128+8 halves)
#define OAH   0
#define OAL   10240     // 128*80
#define OBH   20480
#define OBL   29184     // +32*272
#define STAGE 37888
#define SMEMB (2*STAGE + 512)

template <int K>
__global__ __launch_bounds__(512, 1)
void gemm1_kernel(const float* __restrict__ A, long lda,
                  const float* __restrict__ B,
                  __half* __restrict__ C)
{
    extern __shared__ char smem[];
    constexpr int NCH = K / 32;

    const int tid = threadIdx.x;
    const int l   = tid & 31;
    const int wid = tid >> 5;
    const int wm  = wid >> 2;
    const int wn  = wid & 3;

    const float* Ag = A + (size_t)blockIdx.x * 128 * lda;
    __half*      Cg = C + (size_t)blockIdx.x * 128 * NH;

    const uint32_t sb = smem_to_u32(smem);

    float c[2][4][4];
    #pragma unroll
    for (int i = 0; i < 2; i++)
        #pragma unroll
        for (int j = 0; j < 4; j++)
            #pragma unroll
            for (int q = 0; q < 4; q++) c[i][j][q] = 0.0f;

    float4 pa[2], pb[2];

    auto loadA = [&](int k0) {
        #pragma unroll
        for (int s = 0; s < 2; s++) {
            int f = s * 512 + tid;
            int r = f >> 3, c4 = f & 7;
            pa[s] = *reinterpret_cast<const float4*>(Ag + (size_t)r * lda + k0 + c4 * 4);
        }
    };
    auto loadB = [&](int k0) {
        #pragma unroll
        for (int s = 0; s < 2; s++) {
            int f = s * 512 + tid;
            int r = f >> 5, c4 = f & 31;
            pb[s] = *reinterpret_cast<const float4*>(B + (size_t)(k0 + r) * NH + c4 * 4);
        }
    };
    auto storeStage = [&](int buf) {
        char* st = smem + buf * STAGE;
        #pragma unroll
        for (int s = 0; s < 2; s++) {
            int f = s * 512 + tid;
            int r = f >> 3, c4 = f & 7;
            uint2 hu, lu; split4(pa[s], hu, lu);
            *reinterpret_cast<uint2*>(st + OAH + r * RSA + c4 * 8) = hu;
            *reinterpret_cast<uint2*>(st + OAL + r * RSA + c4 * 8) = lu;
        }
        #pragma unroll
        for (int s = 0; s < 2; s++) {
            int f = s * 512 + tid;
            int r = f >> 5, c4 = f & 31;
            uint2 hu, lu; split4(pb[s], hu, lu);
            *reinterpret_cast<uint2*>(st + OBH + r * RSB + c4 * 8) = hu;
            *reinterpret_cast<uint2*>(st + OBL + r * RSB + c4 * 8) = lu;
        }
    };
    auto compute = [&](int buf) {
        const uint32_t stg = sb + buf * STAGE;
        #pragma unroll
        for (int ks = 0; ks < 2; ks++) {
            uint32_t ar = stg + OAH + (uint32_t)(wm * 32 + (l & 15)) * RSA + ks * 32 + (l >> 4) * 16;
            uint32_t ah0[4], ah1[4], al0[4], al1[4];
            LDSM4(ah0, ar);
            LDSM4(ah1, ar + 16 * RSA);
            LDSM4(al0, ar + (OAL - OAH));
            LDSM4(al1, ar + (OAL - OAH) + 16 * RSA);
            uint32_t bh[2][4], bl[2][4];
            #pragma unroll
            for (int jp = 0; jp < 2; jp++) {
                uint32_t br = stg + OBH + (uint32_t)(ks * 16 + (l & 15)) * RSB
                            + (uint32_t)(wn * 32 + jp * 16 + (l >> 4) * 8) * 2;
                LDSM4T(bh[jp], br);
                LDSM4T(bl[jp], br + (OBL - OBH));
            }
            #pragma unroll
            for (int jp = 0; jp < 2; jp++) {
                const int j0 = jp * 2, j1 = jp * 2 + 1;
                MMA16816(c[0][j0], ah0, bh[jp][0], bh[jp][1]);
                MMA16816(c[1][j0], ah1, bh[jp][0], bh[jp][1]);
                MMA16816(c[0][j1], ah0, bh[jp][2], bh[jp][3]);
                MMA16816(c[1][j1], ah1, bh[jp][2], bh[jp][3]);
                MMA16816(c[0][j0], ah0, bl[jp][0], bl[jp][1]);
                MMA16816(c[1][j0], ah1, bl[jp][0], bl[jp][1]);
                MMA16816(c[0][j1], ah0, bl[jp][2], bl[jp][3]);
                MMA16816(c[1][j1], ah1, bl[jp][2], bl[jp][3]);
                MMA16816(c[0][j0], al0, bh[jp][0], bh[jp][1]);
                MMA16816(c[1][j0], al1, bh[jp][0], bh[jp][1]);
                MMA16816(c[0][j1], al0, bh[jp][2], bh[jp][3]);
                MMA16816(c[1][j1], al1, bh[jp][2], bh[jp][3]);
            }
        }
    };

    loadA(0); loadB(0);
    storeStage(0);
    if (NCH > 1) { loadA(32); loadB(32); }
    __syncthreads();

    for (int ch = 0; ch < NCH; ch++) {
        if (ch + 1 < NCH) storeStage((ch + 1) & 1);
        compute(ch & 1);
        if (ch + 2 < NCH) { loadA((ch + 2) * 32); loadB((ch + 2) * 32); }
        __syncthreads();
    }

    // epilogue: fp16 store (same __float2half_rn the old GEMM-2 B-split applied)
    #pragma unroll
    for (int i = 0; i < 2; i++) {
        const int r0 = wm * 32 + i * 16 + (l >> 2);
        #pragma unroll
        for (int j = 0; j < 4; j++) {
            const int col = wn * 32 + j * 8 + (l & 3) * 2;
            __half2 h0 = __halves2half2(__float2half_rn(c[i][j][0]), __float2half_rn(c[i][j][1]));
            __half2 h1 = __halves2half2(__float2half_rn(c[i][j][2]), __float2half_rn(c[i][j][3]));
            *reinterpret_cast<__half2*>(Cg + (size_t)r0 * NH + col)       = h0;
            *reinterpret_cast<__half2*>(Cg + (size_t)(r0 + 8) * NH + col) = h1;
        }
    }
}

// ===========================================================================
// GEMM-2 (single-pass fp16): out = relu(adj @ support + b)
//   CTA: 128x128, 512 threads = 16 warps (4m x 4n), warp tile 32x32, BK=32.
//   A (adj, fp32): LDG -> split4hi -> STS, double-buffered (register pipeline).
//   B (support, ALREADY fp16 in gmem): cp.async gmem->smem, 3-stage ring,
//     one commit group per chunk, wait_group 1 before each end-of-iter sync.
//     No B registers, no B conversion, no B STS.
// ===========================================================================
#define G2_OA0   0
#define G2_ASTG  10240              // 128 rows * RSA
#define G2_OB0   20480              // 2 A bufs
#define G2_BSTG  8704               // 32 rows * RSB
#define G2_BIAS  (G2_OB0 + 3*G2_BSTG)   // 46592
#define G2_SMEM  (G2_BIAS + 512)

__global__ __launch_bounds__(512, 1)
void gemm2_kernel(const float* __restrict__ adj,
                  const __half* __restrict__ Bh_g,
                  float* __restrict__ out,
                  const float* __restrict__ bias)
{
    extern __shared__ char smem[];
    constexpr int NCH = NN / 32;    // 32 k per chunk, 32 chunks? no: 1024/32 = 32... K=NN=1024 -> 32 chunks

    const int tid = threadIdx.x;
    const int l   = tid & 31;
    const int wid = tid >> 5;
    const int wm  = wid >> 2;
    const int wn  = wid & 3;
    const int b   = blockIdx.y;
    const int m0  = blockIdx.x * 128;

    const float* Ag = adj  + (size_t)b * NN * NN + (size_t)m0 * NN;
    const __half* Bg = Bh_g + (size_t)b * NN * NH;
    float*       Cg = out  + (size_t)b * NN * NH + (size_t)m0 * NH;

    float* bias_s = reinterpret_cast<float*>(smem + G2_BIAS);
    if (tid < NH) bias_s[tid] = bias[tid];

    const uint32_t sb = smem_to_u32(smem);

    float c[2][4][4];
    #pragma unroll
    for (int i = 0; i < 2; i++)
        #pragma unroll
        for (int j = 0; j < 4; j++)
            #pragma unroll
            for (int q = 0; q < 4; q++) c[i][j][q] = 0.0f;

    float4 pa[2];

    auto loadA = [&](int k0) {
        #pragma unroll
        for (int s = 0; s < 2; s++) {
            int f = s * 512 + tid;
            int r = f >> 3, c4 = f & 7;
            pa[s] = *reinterpret_cast<const float4*>(Ag + (size_t)r * NN + k0 + c4 * 4);
        }
    };
    auto storeA = [&](int buf) {
        char* st = smem + G2_OA0 + buf * G2_ASTG;
        #pragma unroll
        for (int s = 0; s < 2; s++) {
            int f = s * 512 + tid;
            int r = f >> 3, c4 = f & 7;
            uint2 hu; split4hi(pa[s], hu);
            *reinterpret_cast<uint2*>(st + r * RSA + c4 * 8) = hu;
        }
    };
    // B chunk ch -> stage ch%3 via cp.async (8 KB, 16 B per thread)
    auto issueB = [&](int ch) {
        uint32_t dst = sb + G2_OB0 + (ch % 3) * G2_BSTG
                     + (uint32_t)(tid >> 4) * RSB + (tid & 15) * 16;
        const __half* src = Bg + (size_t)(ch * 32 + (tid >> 4)) * NH + (tid & 15) * 8;
        CP_ASYNC16(dst, src);
        CP_COMMIT();
    };
    auto compute = [&](int ch) {
        const uint32_t sa  = sb + G2_OA0 + (ch & 1) * G2_ASTG;
        const uint32_t sB  = sb + G2_OB0 + (ch % 3) * G2_BSTG;
        #pragma unroll
        for (int ks = 0; ks < 2; ks++) {
            uint32_t ar = sa + (uint32_t)(wm * 32 + (l & 15)) * RSA + ks * 32 + (l >> 4) * 16;
            uint32_t ah0[4], ah1[4];
            LDSM4(ah0, ar);
            LDSM4(ah1, ar + 16 * RSA);
            uint32_t bh[2][4];
            #pragma unroll
            for (int jp = 0; jp < 2; jp++) {
                uint32_t br = sB + (uint32_t)(ks * 16 + (l & 15)) * RSB
                            + (uint32_t)(wn * 32 + jp * 16 + (l >> 4) * 8) * 2;
                LDSM4T(bh[jp], br);
            }
            #pragma unroll
            for (int jp = 0; jp < 2; jp++) {
                const int j0 = jp * 2, j1 = jp * 2 + 1;
                MMA16816(c[0][j0], ah0, bh[jp][0], bh[jp][1]);
                MMA16816(c[1][j0], ah1, bh[jp][0], bh[jp][1]);
                MMA16816(c[0][j1], ah0, bh[jp][2], bh[jp][3]);
                MMA16816(c[1][j1], ah1, bh[jp][2], bh[jp][3]);
            }
        }
    };

    // -------- pipeline --------
    loadA(0); issueB(0);
    storeA(0);
    loadA(32);                 // chunk 1 into regs
    issueB(1);
    CP_WAIT1();                // B0 landed (B1 may be in flight)
    __syncthreads();

    #pragma unroll
    for (int ch = 0; ch < NCH; ch++) {
        if (ch + 1 < NCH) storeA((ch + 1) & 1);
        compute(ch);
        if (ch + 2 < NCH) {
            loadA((ch + 2) * 32);
            issueB(ch + 2);    // stage (ch+2)%3: last read by compute(ch-1), synced
            CP_WAIT1();        // B(ch+1) landed
        } else {
            CP_WAIT0();        // drain tail
        }
        __syncthreads();
    }

    // -------- epilogue --------
    #pragma unroll
    for (int i = 0; i < 2; i++) {
        const int r0 = wm * 32 + i * 16 + (l >> 2);
        #pragma unroll
        for (int j = 0; j < 4; j++) {
            const int col = wn * 32 + j * 8 + (l & 3) * 2;
            const float b0 = bias_s[col], b1 = bias_s[col + 1];
            float2 v0, v1;
            v0.x = fmaxf(c[i][j][0] + b0, 0.0f); v0.y = fmaxf(c[i][j][1] + b1, 0.0f);
            v1.x = fmaxf(c[i][j][2] + b0, 0.0f); v1.y = fmaxf(c[i][j][3] + b1, 0.0f);
            *reinterpret_cast<float2*>(Cg + (size_t)r0 * NH + col)       = v0;
            *reinterpret_cast<float2*>(Cg + (size_t)(r0 + 8) * NH + col) = v1;
        }
    }
}

// ===========================================================================
// Launch
// ===========================================================================
extern "C" void kernel_launch(void* const* d_in, const int* in_sizes, int n_in,
                              void* d_out, int out_size)
{
    const float* x   = (const float*)d_in[0];
    const float* adj = (const float*)d_in[1];
    const float* W   = (const float*)d_in[2];
    const float* b   = (const float*)d_in[3];
    float* out = (float*)d_out;

    __half* support = nullptr;
    cudaGetSymbolAddress((void**)&support, g_support_h);

    cudaFuncSetAttribute(gemm1_kernel<NF>,
                         cudaFuncAttributeMaxDynamicSharedMemorySize, SMEMB);
    cudaFuncSetAttribute(gemm2_kernel,
                         cudaFuncAttributeMaxDynamicSharedMemorySize, G2_SMEM);

    // GEMM-1: support_h = fp16(x @ W)   (x as flat [32768, 128]; 3-pass)
    gemm1_kernel<NF><<<dim3(NB * NN / 128, 1), 512, SMEMB>>>(x, NF, W, support);

    // GEMM-2: out = relu(adj @ support + b)   (1-pass; B via cp.async)
    gemm2_kernel<<<dim3(NN / 128, NB), 512, G2_SMEM>>>(adj, support, out, b);
}

// round 14
// speedup vs baseline: 1.0787x; 1.0787x over previous
#include <cuda_runtime.h>
#include <cuda_fp16.h>
#include <cstdint>

// Problem constants
#define NB   32      // batch
#define NN   1024    // nodes per graph
#define NF   128     // in features
#define NH   128     // hidden features

// fp16 scratch for support = fp16(x @ W)  (static -> allocation-guard safe)
__device__ __half g_support_h[(size_t)NB * NN * NH];   // 8 MB

// ===========================================================================
// PTX helpers (baseline sm_80-class instructions -> compile on compute_103)
// ===========================================================================
__device__ __forceinline__ uint32_t smem_to_u32(const void* p) {
    uint32_t a;
    asm("{ .reg .u64 t; cvta.to.shared.u64 t, %1; cvt.u32.u64 %0, t; }" : "=r"(a) : "l"(p));
    return a;
}

#define LDSM4(R, addr) \
    asm volatile("ldmatrix.sync.aligned.m8n8.x4.shared.b16 {%0,%1,%2,%3}, [%4];" \
        : "=r"((R)[0]), "=r"((R)[1]), "=r"((R)[2]), "=r"((R)[3]) : "r"(addr))

#define LDSM4T(R, addr) \
    asm volatile("ldmatrix.sync.aligned.m8n8.x4.trans.shared.b16 {%0,%1,%2,%3}, [%4];" \
        : "=r"((R)[0]), "=r"((R)[1]), "=r"((R)[2]), "=r"((R)[3]) : "r"(addr))

#define MMA16816(C, A, b0, b1) \
    asm volatile("mma.sync.aligned.m16n8k16.row.col.f32.f16.f16.f32 " \
        "{%0,%1,%2,%3},{%4,%5,%6,%7},{%8,%9},{%0,%1,%2,%3};" \
        : "+f"((C)[0]), "+f"((C)[1]), "+f"((C)[2]), "+f"((C)[3]) \
        : "r"((A)[0]), "r"((A)[1]), "r"((A)[2]), "r"((A)[3]), "r"(b0), "r"(b1))

__device__ __forceinline__ uint32_t pack_h2(__half a, __half b) {
    __half2 t = __halves2half2(a, b);
    return *reinterpret_cast<uint32_t*>(&t);
}

// fp32 -> (hi fp16, lo fp16) split of a float4
__device__ __forceinline__ void split4(float4 v, uint2& hu, uint2& lu) {
    __half h0 = __float2half_rn(v.x), h1 = __float2half_rn(v.y);
    __half h2 = __float2half_rn(v.z), h3 = __float2half_rn(v.w);
    __half l0 = __float2half_rn(v.x - __half2float(h0));
    __half l1 = __float2half_rn(v.y - __half2float(h1));
    __half l2 = __float2half_rn(v.z - __half2float(h2));
    __half l3 = __float2half_rn(v.w - __half2float(h3));
    hu.x = pack_h2(h0, h1); hu.y = pack_h2(h2, h3);
    lu.x = pack_h2(l0, l1); lu.y = pack_h2(l2, l3);
}

// fp32 -> hi fp16 only
__device__ __forceinline__ void split4hi(float4 v, uint2& hu) {
    hu.x = pack_h2(__float2half_rn(v.x), __float2half_rn(v.y));
    hu.y = pack_h2(__float2half_rn(v.z), __float2half_rn(v.w));
}

// Shared smem row strides
#define RSA   80        // A smem row stride bytes (32+8 halves)
#define RSB   272       // B smem row stride bytes (128+8 halves)

// ===========================================================================
// GEMM-1 (3-pass split-fp16): support_h = fp16(x @ W)
//   M-tile 64, 256 threads = 8 warps (2m x 4n), warp tile 32x32, BK=32, K=128.
//   512 CTAs, ~2 CTAs/SM -> better balance than the old 256x(128-tile) config.
// ===========================================================================
#define G1_OAH   0
#define G1_OAL   5120               // 64*80
#define G1_OBH   10240
#define G1_OBL   18944              // +32*272
#define G1_STAGE 27648
#define G1_SMEM  (2*G1_STAGE + 256)

__global__ __launch_bounds__(256, 2)
void gemm1_kernel(const float* __restrict__ A,
                  const float* __restrict__ B,
                  __half* __restrict__ C)
{
    extern __shared__ char smem[];
    constexpr int NCH = NF / 32;   // 4

    const int tid = threadIdx.x;
    const int l   = tid & 31;
    const int wid = tid >> 5;      // 0..7
    const int wm  = wid >> 2;      // 0..1
    const int wn  = wid & 3;       // 0..3

    const float* Ag = A + (size_t)blockIdx.x * 64 * NF;
    __half*      Cg = C + (size_t)blockIdx.x * 64 * NH;

    const uint32_t sb = smem_to_u32(smem);

    float c[2][4][4];
    #pragma unroll
    for (int i = 0; i < 2; i++)
        #pragma unroll
        for (int j = 0; j < 4; j++)
            #pragma unroll
            for (int q = 0; q < 4; q++) c[i][j][q] = 0.0f;

    float4 pa[2], pb[4];

    auto loadA = [&](int k0) {     // 64x32 fp32 = 512 float4, 2/thread
        #pragma unroll
        for (int s = 0; s < 2; s++) {
            int f = s * 256 + tid;
            int r = f >> 3, c4 = f & 7;
            pa[s] = *reinterpret_cast<const float4*>(Ag + (size_t)r * NF + k0 + c4 * 4);
        }
    };
    auto loadB = [&](int k0) {     // 32x128 fp32 = 1024 float4, 4/thread
        #pragma unroll
        for (int s = 0; s < 4; s++) {
            int f = s * 256 + tid;
            int r = f >> 5, c4 = f & 31;
            pb[s] = *reinterpret_cast<const float4*>(B + (size_t)(k0 + r) * NH + c4 * 4);
        }
    };
    auto storeStage = [&](int buf) {
        char* st = smem + buf * G1_STAGE;
        #pragma unroll
        for (int s = 0; s < 2; s++) {
            int f = s * 256 + tid;
            int r = f >> 3, c4 = f & 7;
            uint2 hu, lu; split4(pa[s], hu, lu);
            *reinterpret_cast<uint2*>(st + G1_OAH + r * RSA + c4 * 8) = hu;
            *reinterpret_cast<uint2*>(st + G1_OAL + r * RSA + c4 * 8) = lu;
        }
        #pragma unroll
        for (int s = 0; s < 4; s++) {
            int f = s * 256 + tid;
            int r = f >> 5, c4 = f & 31;
            uint2 hu, lu; split4(pb[s], hu, lu);
            *reinterpret_cast<uint2*>(st + G1_OBH + r * RSB + c4 * 8) = hu;
            *reinterpret_cast<uint2*>(st + G1_OBL + r * RSB + c4 * 8) = lu;
        }
    };
    auto compute = [&](int buf) {
        const uint32_t stg = sb + buf * G1_STAGE;
        #pragma unroll
        for (int ks = 0; ks < 2; ks++) {
            uint32_t ar = stg + G1_OAH + (uint32_t)(wm * 32 + (l & 15)) * RSA + ks * 32 + (l >> 4) * 16;
            uint32_t ah0[4], ah1[4], al0[4], al1[4];
            LDSM4(ah0, ar);
            LDSM4(ah1, ar + 16 * RSA);
            LDSM4(al0, ar + (G1_OAL - G1_OAH));
            LDSM4(al1, ar + (G1_OAL - G1_OAH) + 16 * RSA);
            uint32_t bh[2][4], bl[2][4];
            #pragma unroll
            for (int jp = 0; jp < 2; jp++) {
                uint32_t br = stg + G1_OBH + (uint32_t)(ks * 16 + (l & 15)) * RSB
                            + (uint32_t)(wn * 32 + jp * 16 + (l >> 4) * 8) * 2;
                LDSM4T(bh[jp], br);
                LDSM4T(bl[jp], br + (G1_OBL - G1_OBH));
            }
            #pragma unroll
            for (int jp = 0; jp < 2; jp++) {
                const int j0 = jp * 2, j1 = jp * 2 + 1;
                MMA16816(c[0][j0], ah0, bh[jp][0], bh[jp][1]);
                MMA16816(c[1][j0], ah1, bh[jp][0], bh[jp][1]);
                MMA16816(c[0][j1], ah0, bh[jp][2], bh[jp][3]);
                MMA16816(c[1][j1], ah1, bh[jp][2], bh[jp][3]);
                MMA16816(c[0][j0], ah0, bl[jp][0], bl[jp][1]);
                MMA16816(c[1][j0], ah1, bl[jp][0], bl[jp][1]);
                MMA16816(c[0][j1], ah0, bl[jp][2], bl[jp][3]);
                MMA16816(c[1][j1], ah1, bl[jp][2], bl[jp][3]);
                MMA16816(c[0][j0], al0, bh[jp][0], bh[jp][1]);
                MMA16816(c[1][j0], al1, bh[jp][0], bh[jp][1]);
                MMA16816(c[0][j1], al0, bh[jp][2], bh[jp][3]);
                MMA16816(c[1][j1], al1, bh[jp][2], bh[jp][3]);
            }
        }
    };

    loadA(0); loadB(0);
    storeStage(0);
    loadA(32); loadB(32);
    __syncthreads();

    for (int ch = 0; ch < NCH; ch++) {
        if (ch + 1 < NCH) storeStage((ch + 1) & 1);
        compute(ch & 1);
        if (ch + 2 < NCH) { loadA((ch + 2) * 32); loadB((ch + 2) * 32); }
        __syncthreads();
    }

    // epilogue: fp16 store (same __float2half_rn rounding as before)
    #pragma unroll
    for (int i = 0; i < 2; i++) {
        const int r0 = wm * 32 + i * 16 + (l >> 2);
        #pragma unroll
        for (int j = 0; j < 4; j++) {
            const int col = wn * 32 + j * 8 + (l & 3) * 2;
            __half2 h0 = __halves2half2(__float2half_rn(c[i][j][0]), __float2half_rn(c[i][j][1]));
            __half2 h1 = __halves2half2(__float2half_rn(c[i][j][2]), __float2half_rn(c[i][j][3]));
            *reinterpret_cast<__half2*>(Cg + (size_t)r0 * NH + col)       = h0;
            *reinterpret_cast<__half2*>(Cg + (size_t)(r0 + 8) * NH + col) = h1;
        }
    }
}

// ===========================================================================
// GEMM-2 (single-pass fp16): out = relu(adj @ support + b)
//   CTA: 128x128, 512 threads = 16 warps (4m x 4n), warp tile 32x32, BK=32.
//   ROUND-12 SCHEDULE (proven): LDG into regs 2 chunks ahead, storeStage
//   interleaved with compute, ONE plain (non-unrolled) loop, one sync/iter.
//   B is already fp16 in gmem: one float4 LDG/thread/chunk, direct STS,
//   no conversion. A: LDG fp32 -> split4hi -> STS.
// ===========================================================================
#define G2_OA    0
#define G2_OB    10240              // A buf = 128*80
#define G2_BSTG  8704               // B buf = 32*272
#define G2_STAGE 18944              // A+B per buffer
#define G2_BIAS  (2*G2_STAGE)       // 37888
#define G2_SMEM  (G2_BIAS + 512)

__global__ __launch_bounds__(512, 1)
void gemm2_kernel(const float* __restrict__ adj,
                  const __half* __restrict__ Bh_g,
                  float* __restrict__ out,
                  const float* __restrict__ bias)
{
    extern __shared__ char smem[];
    constexpr int NCH = NN / 32;    // 32

    const int tid = threadIdx.x;
    const int l   = tid & 31;
    const int wid = tid >> 5;
    const int wm  = wid >> 2;
    const int wn  = wid & 3;
    const int b   = blockIdx.y;
    const int m0  = blockIdx.x * 128;

    const float*  Ag = adj  + (size_t)b * NN * NN + (size_t)m0 * NN;
    const __half* Bg = Bh_g + (size_t)b * NN * NH;
    float*        Cg = out  + (size_t)b * NN * NH + (size_t)m0 * NH;

    float* bias_s = reinterpret_cast<float*>(smem + G2_BIAS);
    if (tid < NH) bias_s[tid] = bias[tid];

    const uint32_t sb = smem_to_u32(smem);

    float c[2][4][4];
    #pragma unroll
    for (int i = 0; i < 2; i++)
        #pragma unroll
        for (int j = 0; j < 4; j++)
            #pragma unroll
            for (int q = 0; q < 4; q++) c[i][j][q] = 0.0f;

    float4 pa[2];   // A: 128x32 fp32 = 1024 float4, 2/thread
    float4 pbv;     // B: 32x128 fp16 = 8 KB, one float4/thread

    auto loadA = [&](int k0) {
        #pragma unroll
        for (int s = 0; s < 2; s++) {
            int f = s * 512 + tid;
            int r = f >> 3, c4 = f & 7;
            pa[s] = *reinterpret_cast<const float4*>(Ag + (size_t)r * NN + k0 + c4 * 4);
        }
    };
    auto loadB = [&](int k0) {
        int r = tid >> 4, cq = tid & 15;     // row 0..31, 16B chunk 0..15
        pbv = *reinterpret_cast<const float4*>(Bg + (size_t)(k0 + r) * NH + cq * 8);
    };
    auto storeStage = [&](int buf) {
        char* st = smem + buf * G2_STAGE;
        #pragma unroll
        for (int s = 0; s < 2; s++) {
            int f = s * 512 + tid;
            int r = f >> 3, c4 = f & 7;
            uint2 hu; split4hi(pa[s], hu);
            *reinterpret_cast<uint2*>(st + G2_OA + r * RSA + c4 * 8) = hu;
        }
        int r = tid >> 4, cq = tid & 15;
        *reinterpret_cast<float4*>(st + G2_OB + r * RSB + cq * 16) = pbv;
    };
    auto compute = [&](int buf) {
        const uint32_t stg = sb + buf * G2_STAGE;
        #pragma unroll
        for (int ks = 0; ks < 2; ks++) {
            uint32_t ar = stg + G2_OA + (uint32_t)(wm * 32 + (l & 15)) * RSA + ks * 32 + (l >> 4) * 16;
            uint32_t ah0[4], ah1[4];
            LDSM4(ah0, ar);
            LDSM4(ah1, ar + 16 * RSA);
            uint32_t bh[2][4];
            #pragma unroll
            for (int jp = 0; jp < 2; jp++) {
                uint32_t br = stg + G2_OB + (uint32_t)(ks * 16 + (l & 15)) * RSB
                            + (uint32_t)(wn * 32 + jp * 16 + (l >> 4) * 8) * 2;
                LDSM4T(bh[jp], br);
            }
            #pragma unroll
            for (int jp = 0; jp < 2; jp++) {
                const int j0 = jp * 2, j1 = jp * 2 + 1;
                MMA16816(c[0][j0], ah0, bh[jp][0], bh[jp][1]);
                MMA16816(c[1][j0], ah1, bh[jp][0], bh[jp][1]);
                MMA16816(c[0][j1], ah0, bh[jp][2], bh[jp][3]);
                MMA16816(c[1][j1], ah1, bh[jp][2], bh[jp][3]);
            }
        }
    };

    // -------- pipeline: one __syncthreads per iteration, plain loop --------
    loadA(0); loadB(0);
    storeStage(0);
    loadA(32); loadB(32);
    __syncthreads();

    for (int ch = 0; ch < NCH; ch++) {
        if (ch + 1 < NCH) storeStage((ch + 1) & 1);
        compute(ch & 1);
        if (ch + 2 < NCH) { loadA((ch + 2) * 32); loadB((ch + 2) * 32); }
        __syncthreads();
    }

    // -------- epilogue --------
    #pragma unroll
    for (int i = 0; i < 2; i++) {
        const int r0 = wm * 32 + i * 16 + (l >> 2);
        #pragma unroll
        for (int j = 0; j < 4; j++) {
            const int col = wn * 32 + j * 8 + (l & 3) * 2;
            const float b0 = bias_s[col], b1 = bias_s[col + 1];
            float2 v0, v1;
            v0.x = fmaxf(c[i][j][0] + b0, 0.0f); v0.y = fmaxf(c[i][j][1] + b1, 0.0f);
            v1.x = fmaxf(c[i][j][2] + b0, 0.0f); v1.y = fmaxf(c[i][j][3] + b1, 0.0f);
            *reinterpret_cast<float2*>(Cg + (size_t)r0 * NH + col)       = v0;
            *reinterpret_cast<float2*>(Cg + (size_t)(r0 + 8) * NH + col) = v1;
        }
    }
}

// ===========================================================================
// Launch
// ===========================================================================
extern "C" void kernel_launch(void* const* d_in, const int* in_sizes, int n_in,
                              void* d_out, int out_size)
{
    const float* x   = (const float*)d_in[0];
    const float* adj = (const float*)d_in[1];
    const float* W   = (const float*)d_in[2];
    const float* b   = (const float*)d_in[3];
    float* out = (float*)d_out;

    __half* support = nullptr;
    cudaGetSymbolAddress((void**)&support, g_support_h);

    cudaFuncSetAttribute(gemm1_kernel,
                         cudaFuncAttributeMaxDynamicSharedMemorySize, G1_SMEM);
    cudaFuncSetAttribute(gemm2_kernel,
                         cudaFuncAttributeMaxDynamicSharedMemorySize, G2_SMEM);

    // GEMM-1: support_h = fp16(x @ W)   (x as flat [32768, 128]; 3-pass, M-tile 64)
    gemm1_kernel<<<dim3(NB * NN / 64, 1), 256, G1_SMEM>>>(x, W, support);

    // GEMM-2: out = relu(adj @ support + b)   (1-pass; fp16 B direct)
    gemm2_kernel<<<dim3(NN / 128, NB), 512, G2_SMEM>>>(adj, support, out, b);
}